// round 8
// baseline (speedup 1.0000x reference)
#include <cuda_runtime.h>
#include <cuda_bf16.h>
#include <cstdint>

#define BATCH 16
#define NV    20000
#define FIN   64
#define COUT  64
#define KNB   16

// Scratch: y = x @ Wn in bf16, packed 2 channels per uint32. [B][V][COUT/2]
__device__ uint32_t g_y[(size_t)BATCH * NV * (COUT / 2)];
// Weights in mma-fragment order: [mat(2)][ks(8)][nt(8)][lane(32)][2] tf32 bits
__device__ uint32_t g_wfrag[2 * 8 * 8 * 32 * 2];

// ---------------------------------------------------------------------------
// Pre-kernel: swizzle Wx/Wn into m16n8k8 B-fragment order (tf32)
// ---------------------------------------------------------------------------
__global__ void wfrag_build_kernel(const float* __restrict__ Wx,
                                   const float* __restrict__ Wn)
{
    int i = blockIdx.x * 256 + threadIdx.x;        // 0..16383
    int j    =  i        & 1;
    int lane = (i >> 1)  & 31;
    int nt   = (i >> 6)  & 7;
    int ks   = (i >> 9)  & 7;
    int mat  =  i >> 12;
    int k = (lane & 3) + 4 * j + 8 * ks;
    int n = (lane >> 2) + 8 * nt;
    const float* W = mat ? Wn : Wx;
    float v = W[k * COUT + n];
    uint32_t tv;
    asm("cvt.rna.tf32.f32 %0, %1;" : "=r"(tv) : "f"(v));
    g_wfrag[i] = tv;
}

// ---------------------------------------------------------------------------
// Kernel A: tensor-core dual GEMM. out = x@Wx + b (d_out), y = x@Wn (bf16)
// CTA = 128 verts x 64 cols, 8 warps; warp = 16 verts x 64 cols, K=64.
// ---------------------------------------------------------------------------
__global__ __launch_bounds__(256)
void gemm_tc_kernel(const float* __restrict__ x,
                    const float* __restrict__ bias,
                    float*       __restrict__ out)
{
    __shared__ uint32_t sW[2 * 8 * 8 * 32 * 2];    // 32 KB

    const int tid = threadIdx.x;

    // Stage fragment-ordered weights: 2048 uint4, 8 per thread, coalesced.
    {
        const uint4* src = (const uint4*)g_wfrag;
        uint4*       dst = (uint4*)sW;
        #pragma unroll
        for (int i = 0; i < 8; ++i)
            dst[tid + i * 256] = src[tid + i * 256];
    }
    __syncthreads();

    const int lane = tid & 31;
    const int wid  = tid >> 5;
    const int g    = lane >> 2;      // group id (row within m-tile)
    const int t    = lane & 3;       // thread-in-group (col phase)
    const int b    = blockIdx.y;
    const int vb   = blockIdx.x * 128 + wid * 16;
    const int r0   = vb + g;
    const int r1   = r0 + 8;

    const float* __restrict__ xb = x + (size_t)b * NV * FIN;

    // ---- Prefetch A: 2 rows x 16 cols (cols == t mod 4). 32 indep LDG.32 --
    float f0[16], f1[16];
    #pragma unroll
    for (int j = 0; j < 16; ++j) {
        int c = t + 4 * j;
        f0[j] = (r0 < NV) ? __ldg(&xb[(size_t)r0 * FIN + c]) : 0.f;
        f1[j] = (r1 < NV) ? __ldg(&xb[(size_t)r1 * FIN + c]) : 0.f;
    }
    uint32_t ar0[16], ar1[16];
    #pragma unroll
    for (int j = 0; j < 16; ++j) {
        asm("cvt.rna.tf32.f32 %0, %1;" : "=r"(ar0[j]) : "f"(f0[j]));
        asm("cvt.rna.tf32.f32 %0, %1;" : "=r"(ar1[j]) : "f"(f1[j]));
    }

    // ---- Mainloop: 8 k-steps x 8 n-tiles x 2 matrices ----------------------
    float accX[8][4] = {{0.f}};
    float accN[8][4] = {{0.f}};

    #pragma unroll
    for (int ks = 0; ks < 8; ++ks) {
        const uint32_t a0 = ar0[2 * ks];
        const uint32_t a1 = ar1[2 * ks];
        const uint32_t a2 = ar0[2 * ks + 1];
        const uint32_t a3 = ar1[2 * ks + 1];

        #pragma unroll
        for (int nt = 0; nt < 8; ++nt) {
            const uint2 bx = *(const uint2*)&sW[((0 * 8 + ks) * 8 + nt) * 64 + lane * 2];
            const uint2 bn = *(const uint2*)&sW[((1 * 8 + ks) * 8 + nt) * 64 + lane * 2];

            asm volatile(
                "mma.sync.aligned.m16n8k8.row.col.f32.tf32.tf32.f32 "
                "{%0,%1,%2,%3}, {%4,%5,%6,%7}, {%8,%9}, {%0,%1,%2,%3};"
                : "+f"(accX[nt][0]), "+f"(accX[nt][1]),
                  "+f"(accX[nt][2]), "+f"(accX[nt][3])
                : "r"(a0), "r"(a1), "r"(a2), "r"(a3),
                  "r"(bx.x), "r"(bx.y));
            asm volatile(
                "mma.sync.aligned.m16n8k8.row.col.f32.tf32.tf32.f32 "
                "{%0,%1,%2,%3}, {%4,%5,%6,%7}, {%8,%9}, {%0,%1,%2,%3};"
                : "+f"(accN[nt][0]), "+f"(accN[nt][1]),
                  "+f"(accN[nt][2]), "+f"(accN[nt][3])
                : "r"(a0), "r"(a1), "r"(a2), "r"(a3),
                  "r"(bn.x), "r"(bn.y));
        }
    }

    // ---- Epilogue: out fp32; y packed bf16 ---------------------------------
    float*    __restrict__ outb = out + (size_t)b * NV * COUT;
    uint32_t* __restrict__ yb   = g_y + (size_t)b * NV * (COUT / 2);
    #pragma unroll
    for (int nt = 0; nt < 8; ++nt) {
        const int c  = nt * 8 + 2 * t;
        const int ch = nt * 4 + t;        // packed half-index c/2
        const float2 bv = *(const float2*)&bias[c];
        if (r0 < NV) {
            *(float2*)&outb[(size_t)r0 * COUT + c] =
                make_float2(accX[nt][0] + bv.x, accX[nt][1] + bv.y);
            __nv_bfloat162 p = __float22bfloat162_rn(
                make_float2(accN[nt][0], accN[nt][1]));
            yb[(size_t)r0 * (COUT / 2) + ch] = *(uint32_t*)&p;
        }
        if (r1 < NV) {
            *(float2*)&outb[(size_t)r1 * COUT + c] =
                make_float2(accX[nt][2] + bv.x, accX[nt][3] + bv.y);
            __nv_bfloat162 p = __float22bfloat162_rn(
                make_float2(accN[nt][2], accN[nt][3]));
            yb[(size_t)r1 * (COUT / 2) + ch] = *(uint32_t*)&p;
        }
    }
}

// ---------------------------------------------------------------------------
// Kernel B: out[b,v,:] += (1/K) * sum_k y[b, neighbor[v,k]-1, :]   (0 = pad)
// One warp per FOUR vertices. bf16 rows: 128B = 1 L1 line per warp-load.
// Neighbor ids staged in smem; k-loop reads them via LDS broadcast.
// ---------------------------------------------------------------------------
__global__ __launch_bounds__(256)
void gather_add_kernel(const int* __restrict__ neighbor,
                       float*     __restrict__ out)
{
    __shared__ int sN[512];   // 32 verts * 16 ids

    const int tid  = threadIdx.x;
    const int warp = tid >> 5;
    const int lane = tid & 31;
    const int vblk = blockIdx.x * 32;              // 625 * 32 = 20000 exactly
    const int v0   = vblk + warp * 4;
    const int b    = blockIdx.y;

    // Stage this CTA's 512 neighbor ids (one coalesced 2KB read).
    {
        int2 t2 = __ldg((const int2*)&neighbor[vblk * KNB] + tid);
        ((int2*)sN)[tid] = t2;
    }
    __syncthreads();

    const uint32_t* __restrict__ yb = g_y + (size_t)b * NV * (COUT / 2);

    float* __restrict__ op0 = out + ((size_t)b * NV + v0 + 0) * COUT + lane * 2;
    float* __restrict__ op1 = out + ((size_t)b * NV + v0 + 1) * COUT + lane * 2;
    float* __restrict__ op2 = out + ((size_t)b * NV + v0 + 2) * COUT + lane * 2;
    float* __restrict__ op3 = out + ((size_t)b * NV + v0 + 3) * COUT + lane * 2;

    float2 o0 = *(const float2*)op0;   // x@Wx + bias parts
    float2 o1 = *(const float2*)op1;
    float2 o2 = *(const float2*)op2;
    float2 o3 = *(const float2*)op3;

    float2 a0 = make_float2(0.f, 0.f);
    float2 a1 = make_float2(0.f, 0.f);
    float2 a2 = make_float2(0.f, 0.f);
    float2 a3 = make_float2(0.f, 0.f);

    const int nbase = warp * 4 * KNB;

    #pragma unroll
    for (int k = 0; k < KNB; ++k) {
        const int r0 = sN[nbase + 0 * KNB + k];   // LDS broadcast (uniform addr)
        const int r1 = sN[nbase + 1 * KNB + k];
        const int r2 = sN[nbase + 2 * KNB + k];
        const int r3 = sN[nbase + 3 * KNB + k];

        if (r0 > 0) {
            uint32_t w = __ldg(&yb[(size_t)(r0 - 1) * (COUT / 2) + lane]);
            a0.x += __uint_as_float(w << 16);
            a0.y += __uint_as_float(w & 0xffff0000u);
        }
        if (r1 > 0) {
            uint32_t w = __ldg(&yb[(size_t)(r1 - 1) * (COUT / 2) + lane]);
            a1.x += __uint_as_float(w << 16);
            a1.y += __uint_as_float(w & 0xffff0000u);
        }
        if (r2 > 0) {
            uint32_t w = __ldg(&yb[(size_t)(r2 - 1) * (COUT / 2) + lane]);
            a2.x += __uint_as_float(w << 16);
            a2.y += __uint_as_float(w & 0xffff0000u);
        }
        if (r3 > 0) {
            uint32_t w = __ldg(&yb[(size_t)(r3 - 1) * (COUT / 2) + lane]);
            a3.x += __uint_as_float(w << 16);
            a3.y += __uint_as_float(w & 0xffff0000u);
        }
    }

    const float s = 1.0f / (float)KNB;
    o0.x += a0.x * s;  o0.y += a0.y * s;
    o1.x += a1.x * s;  o1.y += a1.y * s;
    o2.x += a2.x * s;  o2.y += a2.y * s;
    o3.x += a3.x * s;  o3.y += a3.y * s;
    *(float2*)op0 = o0;
    *(float2*)op1 = o1;
    *(float2*)op2 = o2;
    *(float2*)op3 = o3;
}

extern "C" void kernel_launch(void* const* d_in, const int* in_sizes, int n_in,
                              void* d_out, int out_size)
{
    // metadata order: x, Wx, Wn, b, neighbor
    const float* x        = (const float*)d_in[0];
    const float* Wx       = (const float*)d_in[1];
    const float* Wn       = (const float*)d_in[2];
    const float* bias     = (const float*)d_in[3];
    const int*   neighbor = (const int*)d_in[4];
    float*       out      = (float*)d_out;

    wfrag_build_kernel<<<64, 256>>>(Wx, Wn);

    dim3 gridA((NV + 127) / 128, BATCH);        // 157 x 16
    gemm_tc_kernel<<<gridA, 256>>>(x, bias, out);

    dim3 gridB(NV / 32, BATCH);                 // 625 x 16
    gather_add_kernel<<<gridB, 256>>>(neighbor, out);
}